// round 1
// baseline (speedup 1.0000x reference)
#include <cuda_runtime.h>
#include <math.h>

#define B_ 8
#define N_ 2048
#define E_ 512
#define F_ 256
#define L_ 2

static __device__ __constant__ float kLnEps = 1e-5f;

// Scratch (no allocations allowed) — ~270 MB total.
__device__ float g_q  [B_ * N_ * F_];
__device__ float g_k  [B_ * N_ * F_];
__device__ float g_s  [B_ * N_ * N_];   // scores / probs (in-place softmax)
__device__ float g_ctx[B_ * N_ * E_];
__device__ float g_c2 [B_ * N_ * E_];
__device__ float g_x  [B_ * N_ * E_];   // ping-pong x between layers

__device__ __forceinline__ float warp_max(float v) {
#pragma unroll
    for (int o = 16; o > 0; o >>= 1) v = fmaxf(v, __shfl_xor_sync(0xffffffffu, v, o));
    return v;
}
__device__ __forceinline__ float warp_sum(float v) {
#pragma unroll
    for (int o = 16; o > 0; o >>= 1) v += __shfl_xor_sync(0xffffffffu, v, o);
    return v;
}

// ============================================================================
// C[M x Nc] = A[M x K] * B[Nc x K]^T (+ bias).  grid = (Nc/64, M/64), 256 thr.
// 64x64 block tile, k-chunk 16, 4x4 register micro-tile per thread.
// ============================================================================
__global__ void __launch_bounds__(256) gemm_nt_bias(
    const float* __restrict__ A, const float* __restrict__ Bm,
    const float* __restrict__ bias, float* __restrict__ C,
    int Nc, int K)
{
    __shared__ float As[16][64];   // [k][row]
    __shared__ float Bs[16][64];   // [k][col]
    const int tid = threadIdx.x;
    const int tx = tid & 15, ty = tid >> 4;
    const int row0 = blockIdx.y * 64, col0 = blockIdx.x * 64;
    const int lr = tid >> 2, lc = (tid & 3) << 2;

    float acc[4][4] = {};
    const float* Aptr = A + (size_t)(row0 + lr) * K + lc;
    const float* Bptr = Bm + (size_t)(col0 + lr) * K + lc;

    for (int k0 = 0; k0 < K; k0 += 16) {
        float4 av = *reinterpret_cast<const float4*>(Aptr + k0);
        float4 bv = *reinterpret_cast<const float4*>(Bptr + k0);
        __syncthreads();
        As[lc + 0][lr] = av.x; As[lc + 1][lr] = av.y;
        As[lc + 2][lr] = av.z; As[lc + 3][lr] = av.w;
        Bs[lc + 0][lr] = bv.x; Bs[lc + 1][lr] = bv.y;
        Bs[lc + 2][lr] = bv.z; Bs[lc + 3][lr] = bv.w;
        __syncthreads();
#pragma unroll
        for (int kk = 0; kk < 16; kk++) {
            float4 a4 = *reinterpret_cast<const float4*>(&As[kk][ty << 2]);
            float4 b4 = *reinterpret_cast<const float4*>(&Bs[kk][tx << 2]);
            float ar[4] = {a4.x, a4.y, a4.z, a4.w};
            float br[4] = {b4.x, b4.y, b4.z, b4.w};
#pragma unroll
            for (int i = 0; i < 4; i++)
#pragma unroll
                for (int j = 0; j < 4; j++)
                    acc[i][j] = fmaf(ar[i], br[j], acc[i][j]);
        }
    }

    float bv4[4] = {0.f, 0.f, 0.f, 0.f};
    if (bias) {
#pragma unroll
        for (int j = 0; j < 4; j++) bv4[j] = bias[col0 + (tx << 2) + j];
    }
#pragma unroll
    for (int i = 0; i < 4; i++) {
        float* crow = C + (size_t)(row0 + (ty << 2) + i) * Nc + col0 + (tx << 2);
        float4 o;
        o.x = acc[i][0] + bv4[0]; o.y = acc[i][1] + bv4[1];
        o.z = acc[i][2] + bv4[2]; o.w = acc[i][3] + bv4[3];
        *reinterpret_cast<float4*>(crow) = o;
    }
}

// ============================================================================
// Scores: per batch b, S = Q[b] * K[b]^T / 16, masked (-1e10 where no edge).
// grid = (N/64, N/64, B), 256 thr.
// ============================================================================
__global__ void __launch_bounds__(256) gemm_scores(
    const float* __restrict__ Q, const float* __restrict__ Kt,
    const int* __restrict__ rel, float* __restrict__ S)
{
    __shared__ float As[16][64];
    __shared__ float Bs[16][64];
    const int b = blockIdx.z;
    const float* A  = Q  + (size_t)b * N_ * F_;
    const float* Bm = Kt + (size_t)b * N_ * F_;
    const int tid = threadIdx.x;
    const int tx = tid & 15, ty = tid >> 4;
    const int row0 = blockIdx.y * 64, col0 = blockIdx.x * 64;
    const int lr = tid >> 2, lc = (tid & 3) << 2;

    float acc[4][4] = {};
    const float* Aptr = A + (size_t)(row0 + lr) * F_ + lc;
    const float* Bptr = Bm + (size_t)(col0 + lr) * F_ + lc;

    for (int k0 = 0; k0 < F_; k0 += 16) {
        float4 av = *reinterpret_cast<const float4*>(Aptr + k0);
        float4 bv = *reinterpret_cast<const float4*>(Bptr + k0);
        __syncthreads();
        As[lc + 0][lr] = av.x; As[lc + 1][lr] = av.y;
        As[lc + 2][lr] = av.z; As[lc + 3][lr] = av.w;
        Bs[lc + 0][lr] = bv.x; Bs[lc + 1][lr] = bv.y;
        Bs[lc + 2][lr] = bv.z; Bs[lc + 3][lr] = bv.w;
        __syncthreads();
#pragma unroll
        for (int kk = 0; kk < 16; kk++) {
            float4 a4 = *reinterpret_cast<const float4*>(&As[kk][ty << 2]);
            float4 b4 = *reinterpret_cast<const float4*>(&Bs[kk][tx << 2]);
            float ar[4] = {a4.x, a4.y, a4.z, a4.w};
            float br[4] = {b4.x, b4.y, b4.z, b4.w};
#pragma unroll
            for (int i = 0; i < 4; i++)
#pragma unroll
                for (int j = 0; j < 4; j++)
                    acc[i][j] = fmaf(ar[i], br[j], acc[i][j]);
        }
    }

#pragma unroll
    for (int i = 0; i < 4; i++) {
        const int row = row0 + (ty << 2) + i;
        const size_t off = ((size_t)b * N_ + row) * N_ + col0 + (tx << 2);
        const int4 e = *reinterpret_cast<const int4*>(rel + off);
        float4 o;
        o.x = (e.x == 0) ? -1e10f : acc[i][0] * 0.0625f;
        o.y = (e.y == 0) ? -1e10f : acc[i][1] * 0.0625f;
        o.z = (e.z == 0) ? -1e10f : acc[i][2] * 0.0625f;
        o.w = (e.w == 0) ? -1e10f : acc[i][3] * 0.0625f;
        *reinterpret_cast<float4*>(S + off) = o;
    }
}

// ============================================================================
// Row softmax in place over rows of length N_ (2048). One block per row.
// Masked entries (-1e10) underflow to exactly 0 after exp — matches reference.
// ============================================================================
__global__ void __launch_bounds__(256) softmax_rows(float* __restrict__ S)
{
    __shared__ float red[8];
    float4* row = reinterpret_cast<float4*>(S + (size_t)blockIdx.x * N_);
    const int t = threadIdx.x;
    float4 v0 = row[t];
    float4 v1 = row[t + 256];

    float m = fmaxf(fmaxf(fmaxf(v0.x, v0.y), fmaxf(v0.z, v0.w)),
                    fmaxf(fmaxf(v1.x, v1.y), fmaxf(v1.z, v1.w)));
    m = warp_max(m);
    if ((t & 31) == 0) red[t >> 5] = m;
    __syncthreads();
    m = red[0];
#pragma unroll
    for (int i = 1; i < 8; i++) m = fmaxf(m, red[i]);
    __syncthreads();

    v0.x = expf(v0.x - m); v0.y = expf(v0.y - m);
    v0.z = expf(v0.z - m); v0.w = expf(v0.w - m);
    v1.x = expf(v1.x - m); v1.y = expf(v1.y - m);
    v1.z = expf(v1.z - m); v1.w = expf(v1.w - m);

    float s = warp_sum(v0.x + v0.y + v0.z + v0.w + v1.x + v1.y + v1.z + v1.w);
    if ((t & 31) == 0) red[t >> 5] = s;
    __syncthreads();
    s = red[0];
#pragma unroll
    for (int i = 1; i < 8; i++) s += red[i];
    const float inv = 1.0f / s;

    v0.x *= inv; v0.y *= inv; v0.z *= inv; v0.w *= inv;
    v1.x *= inv; v1.y *= inv; v1.z *= inv; v1.w *= inv;
    row[t] = v0;
    row[t + 256] = v1;
}

// ============================================================================
// ctx = P @ x per batch (NN gemm). grid = (E/64, N/64, B), 256 thr.
// ============================================================================
__global__ void __launch_bounds__(256) gemm_av(
    const float* __restrict__ P, const float* __restrict__ X,
    float* __restrict__ C)
{
    __shared__ float As[16][64];   // [k][row]  (P transposed tile)
    __shared__ float Bs[16][64];   // [k][col]  (X tile, natural)
    const int b = blockIdx.z;
    const float* Pb = P + (size_t)b * N_ * N_;
    const float* Xb = X + (size_t)b * N_ * E_;
    const int tid = threadIdx.x;
    const int tx = tid & 15, ty = tid >> 4;
    const int row0 = blockIdx.y * 64, col0 = blockIdx.x * 64;
    const int alr = tid >> 2, alc = (tid & 3) << 2;
    const int bxr = tid >> 4, bxc = (tid & 15) << 2;

    float acc[4][4] = {};
    for (int k0 = 0; k0 < N_; k0 += 16) {
        float4 av = *reinterpret_cast<const float4*>(Pb + (size_t)(row0 + alr) * N_ + k0 + alc);
        float4 bv = *reinterpret_cast<const float4*>(Xb + (size_t)(k0 + bxr) * E_ + col0 + bxc);
        __syncthreads();
        As[alc + 0][alr] = av.x; As[alc + 1][alr] = av.y;
        As[alc + 2][alr] = av.z; As[alc + 3][alr] = av.w;
        *reinterpret_cast<float4*>(&Bs[bxr][bxc]) = bv;
        __syncthreads();
#pragma unroll
        for (int kk = 0; kk < 16; kk++) {
            float4 a4 = *reinterpret_cast<const float4*>(&As[kk][ty << 2]);
            float4 b4 = *reinterpret_cast<const float4*>(&Bs[kk][tx << 2]);
            float ar[4] = {a4.x, a4.y, a4.z, a4.w};
            float br[4] = {b4.x, b4.y, b4.z, b4.w};
#pragma unroll
            for (int i = 0; i < 4; i++)
#pragma unroll
                for (int j = 0; j < 4; j++)
                    acc[i][j] = fmaf(ar[i], br[j], acc[i][j]);
        }
    }
#pragma unroll
    for (int i = 0; i < 4; i++) {
        float* crow = C + ((size_t)b * N_ + row0 + (ty << 2) + i) * E_ + col0 + (tx << 2);
        float4 o; o.x = acc[i][0]; o.y = acc[i][1]; o.z = acc[i][2]; o.w = acc[i][3];
        *reinterpret_cast<float4*>(crow) = o;
    }
}

// ============================================================================
// out = LayerNorm(x + c2) * gamma + beta, rows of E_ (512). One block per row.
// ============================================================================
__global__ void __launch_bounds__(128) resid_ln(
    const float* __restrict__ x, const float* __restrict__ c2,
    const float* __restrict__ gam, const float* __restrict__ bet,
    float* __restrict__ out)
{
    __shared__ float red[4];
    const size_t base = (size_t)blockIdx.x * E_;
    const int t = threadIdx.x;
    float4 xv = *reinterpret_cast<const float4*>(x + base + (t << 2));
    float4 cv = *reinterpret_cast<const float4*>(c2 + base + (t << 2));
    float v0 = xv.x + cv.x, v1 = xv.y + cv.y, v2 = xv.z + cv.z, v3 = xv.w + cv.w;

    float s = warp_sum(v0 + v1 + v2 + v3);
    if ((t & 31) == 0) red[t >> 5] = s;
    __syncthreads();
    const float mean = (red[0] + red[1] + red[2] + red[3]) * (1.0f / E_);
    __syncthreads();

    float d0 = v0 - mean, d1 = v1 - mean, d2 = v2 - mean, d3 = v3 - mean;
    float ss = warp_sum(d0 * d0 + d1 * d1 + d2 * d2 + d3 * d3);
    if ((t & 31) == 0) red[t >> 5] = ss;
    __syncthreads();
    const float var = (red[0] + red[1] + red[2] + red[3]) * (1.0f / E_);
    const float r = rsqrtf(var + kLnEps);

    float4 gv = *reinterpret_cast<const float4*>(gam + (t << 2));
    float4 bv = *reinterpret_cast<const float4*>(bet + (t << 2));
    float4 o;
    o.x = d0 * r * gv.x + bv.x;
    o.y = d1 * r * gv.y + bv.y;
    o.z = d2 * r * gv.z + bv.z;
    o.w = d3 * r * gv.w + bv.w;
    *reinterpret_cast<float4*>(out + base + (t << 2)) = o;
}

// ============================================================================
// Launch
// ============================================================================
extern "C" void kernel_launch(void* const* d_in, const int* in_sizes, int n_in,
                              void* d_out, int out_size)
{
    const float* node = (const float*)d_in[0];
    const int*   rel  = (const int*)d_in[1];
    const float* Wq   = (const float*)d_in[2];
    const float* bq   = (const float*)d_in[3];
    const float* Wk   = (const float*)d_in[4];
    const float* bk   = (const float*)d_in[5];
    const float* Wc   = (const float*)d_in[6];
    const float* lng  = (const float*)d_in[7];
    const float* lnb  = (const float*)d_in[8];
    float* out = (float*)d_out;

    float *qp, *kp, *sp, *ctxp, *c2p, *xp;
    cudaGetSymbolAddress((void**)&qp,   g_q);
    cudaGetSymbolAddress((void**)&kp,   g_k);
    cudaGetSymbolAddress((void**)&sp,   g_s);
    cudaGetSymbolAddress((void**)&ctxp, g_ctx);
    cudaGetSymbolAddress((void**)&c2p,  g_c2);
    cudaGetSymbolAddress((void**)&xp,   g_x);

    const int M = B_ * N_;
    const float* x_in = node;
    for (int l = 0; l < L_; l++) {
        float* x_out = (l == L_ - 1) ? out : xp;

        // q = x Wq^T + bq ; k = x Wk^T + bk
        gemm_nt_bias<<<dim3(F_ / 64, M / 64), 256>>>(
            x_in, Wq + (size_t)l * F_ * E_, bq + l * F_, qp, F_, E_);
        gemm_nt_bias<<<dim3(F_ / 64, M / 64), 256>>>(
            x_in, Wk + (size_t)l * F_ * E_, bk + l * F_, kp, F_, E_);

        // scores = q k^T / 16, masked
        gemm_scores<<<dim3(N_ / 64, N_ / 64, B_), 256>>>(qp, kp, rel, sp);

        // softmax over keys
        softmax_rows<<<M, 256>>>(sp);

        // ctx = P @ x
        gemm_av<<<dim3(E_ / 64, N_ / 64, B_), 256>>>(sp, x_in, ctxp);

        // c2 = ctx Wc^T
        gemm_nt_bias<<<dim3(E_ / 64, M / 64), 256>>>(
            ctxp, Wc + (size_t)l * E_ * E_, nullptr, c2p, E_, E_);

        // x = LN(x + c2)
        resid_ln<<<M, 128>>>(x_in, c2p, lng + l * E_, lnb + l * E_, x_out);

        x_in = x_out;
    }
}

// round 2
// speedup vs baseline: 1.1728x; 1.1728x over previous
#include <cuda_runtime.h>
#include <math.h>

#define B_ 8
#define N_ 2048
#define E_ 512
#define F_ 256
#define L_ 2

static __device__ __constant__ float kLnEps = 1e-5f;

// Scratch (no allocations allowed).
__device__ float g_q  [B_ * N_ * F_];
__device__ float g_k  [B_ * N_ * F_];
__device__ float g_s  [B_ * N_ * N_];   // scores / probs (in-place softmax)
__device__ float g_ctx[B_ * N_ * E_];
__device__ float g_c2 [B_ * N_ * E_];
__device__ float g_x  [B_ * N_ * E_];   // ping-pong x between layers

__device__ __forceinline__ float warp_max(float v) {
#pragma unroll
    for (int o = 16; o > 0; o >>= 1) v = fmaxf(v, __shfl_xor_sync(0xffffffffu, v, o));
    return v;
}
__device__ __forceinline__ float warp_sum(float v) {
#pragma unroll
    for (int o = 16; o > 0; o >>= 1) v += __shfl_xor_sync(0xffffffffu, v, o);
    return v;
}

__device__ __forceinline__ unsigned f2t(float x) {
    unsigned r;
    asm("cvt.rna.tf32.f32 %0, %1;" : "=r"(r) : "f"(x));
    return r;
}

#define MMA_TF32(d, a, b)                                                     \
    asm volatile(                                                             \
        "mma.sync.aligned.m16n8k8.row.col.f32.tf32.tf32.f32 "                 \
        "{%0,%1,%2,%3},{%4,%5,%6,%7},{%8,%9},{%0,%1,%2,%3};"                  \
        : "+f"(d[0]), "+f"(d[1]), "+f"(d[2]), "+f"(d[3])                      \
        : "r"(a[0]), "r"(a[1]), "r"(a[2]), "r"(a[3]), "r"(b[0]), "r"(b[1]))

// ============================================================================
// Tensor-core GEMM, 3xTF32 (fp32 accuracy).
//   BNT=true : C = A[M,K] * Bg[Nc,K]^T    (B tile stored [n][k])
//   BNT=false: C = A[M,K] * Bg[K,Nc]      (B tile stored [k][n])
//   EPI: 0 none, 1 +bias[col], 2 mask(rel==0 -> -1e10) + *0.0625
// Block tile 128x64, BK=16, 8 warps (32x32 warp tiles). grid=(Nc/64, M/128, Z)
// ============================================================================
template <bool BNT, int EPI>
__global__ void __launch_bounds__(256) mma_gemm(
    const float* __restrict__ A, const float* __restrict__ Bg,
    const float* __restrict__ bias, const int* __restrict__ rel,
    float* __restrict__ C, int K, int ldB, int ldC,
    long sA, long sB, long sC, long sR)
{
    constexpr int BROWS = BNT ? 64 : 16;
    constexpr int BSTR  = BNT ? 20 : 68;
    __shared__ float As_h[128][20], As_l[128][20];
    __shared__ float Bs_h[BROWS][BSTR], Bs_l[BROWS][BSTR];

    const int z = blockIdx.z;
    A  += (size_t)z * sA;
    Bg += (size_t)z * sB;
    C  += (size_t)z * sC;

    const int tid = threadIdx.x, lane = tid & 31, wid = tid >> 5;
    const int wm = (wid & 3) * 32, wn = (wid >> 2) * 32;
    const int bm = blockIdx.y * 128, bn = blockIdx.x * 64;

    // G->S loader indices
    const int ar = tid >> 2, ac = (tid & 3) << 2;                   // A: 64 rows/pass
    const int br = BNT ? (tid >> 2) : (tid >> 4);
    const int bc = BNT ? ((tid & 3) << 2) : ((tid & 15) << 2);

    const float* Ap0 = A + (size_t)(bm + ar) * K + ac;
    const float* Ap1 = A + (size_t)(bm + ar + 64) * K + ac;
    const float* Bp  = BNT ? (Bg + (size_t)(bn + br) * ldB + bc)
                           : (Bg + (size_t)br * ldB + bn + bc);

    float acc[2][4][4];
#pragma unroll
    for (int i = 0; i < 2; i++)
#pragma unroll
        for (int j = 0; j < 4; j++)
#pragma unroll
            for (int p = 0; p < 4; p++) acc[i][j][p] = 0.0f;

    float4 ra0 = *reinterpret_cast<const float4*>(Ap0);
    float4 ra1 = *reinterpret_cast<const float4*>(Ap1);
    float4 rb  = *reinterpret_cast<const float4*>(Bp);

    const int fr = lane >> 2, fc = lane & 3;  // fragment row/col within quad map

    for (int k0 = 16;; k0 += 16) {
        // split & store current tile
        {
            float va[8] = {ra0.x, ra0.y, ra0.z, ra0.w, ra1.x, ra1.y, ra1.z, ra1.w};
#pragma unroll
            for (int j = 0; j < 8; j++) {
                unsigned hb = f2t(va[j]);
                float hf = __uint_as_float(hb);
                int row = ar + (j >> 2) * 64, col = ac + (j & 3);
                As_h[row][col] = hf;
                As_l[row][col] = __uint_as_float(f2t(va[j] - hf));
            }
            float vb[4] = {rb.x, rb.y, rb.z, rb.w};
#pragma unroll
            for (int j = 0; j < 4; j++) {
                unsigned hb = f2t(vb[j]);
                float hf = __uint_as_float(hb);
                Bs_h[br][bc + j] = hf;
                Bs_l[br][bc + j] = __uint_as_float(f2t(vb[j] - hf));
            }
        }
        __syncthreads();

        const bool more = k0 < K;
        if (more) {
            ra0 = *reinterpret_cast<const float4*>(Ap0 + k0);
            ra1 = *reinterpret_cast<const float4*>(Ap1 + k0);
            rb  = BNT ? *reinterpret_cast<const float4*>(Bp + k0)
                      : *reinterpret_cast<const float4*>(Bp + (size_t)k0 * ldB);
        }

        // compute 2 k-steps of 8 from smem
#pragma unroll
        for (int kk = 0; kk < 2; kk++) {
            unsigned ah[2][4], al[2][4], bh[4][2], bl[4][2];
#pragma unroll
            for (int mt = 0; mt < 2; mt++) {
                int row = wm + mt * 16 + fr;
                int col = kk * 8 + fc;
                ah[mt][0] = __float_as_uint(As_h[row][col]);
                ah[mt][1] = __float_as_uint(As_h[row + 8][col]);
                ah[mt][2] = __float_as_uint(As_h[row][col + 4]);
                ah[mt][3] = __float_as_uint(As_h[row + 8][col + 4]);
                al[mt][0] = __float_as_uint(As_l[row][col]);
                al[mt][1] = __float_as_uint(As_l[row + 8][col]);
                al[mt][2] = __float_as_uint(As_l[row][col + 4]);
                al[mt][3] = __float_as_uint(As_l[row + 8][col + 4]);
            }
#pragma unroll
            for (int nt = 0; nt < 4; nt++) {
                if (BNT) {
                    int row = wn + nt * 8 + fr;
                    int col = kk * 8 + fc;
                    bh[nt][0] = __float_as_uint(Bs_h[row][col]);
                    bh[nt][1] = __float_as_uint(Bs_h[row][col + 4]);
                    bl[nt][0] = __float_as_uint(Bs_l[row][col]);
                    bl[nt][1] = __float_as_uint(Bs_l[row][col + 4]);
                } else {
                    int krow = kk * 8 + fc;
                    int col = wn + nt * 8 + fr;
                    bh[nt][0] = __float_as_uint(Bs_h[krow][col]);
                    bh[nt][1] = __float_as_uint(Bs_h[krow + 4][col]);
                    bl[nt][0] = __float_as_uint(Bs_l[krow][col]);
                    bl[nt][1] = __float_as_uint(Bs_l[krow + 4][col]);
                }
            }
#pragma unroll
            for (int mt = 0; mt < 2; mt++)
#pragma unroll
                for (int nt = 0; nt < 4; nt++) {
                    MMA_TF32(acc[mt][nt], al[mt], bh[nt]);
                    MMA_TF32(acc[mt][nt], ah[mt], bl[nt]);
                    MMA_TF32(acc[mt][nt], ah[mt], bh[nt]);
                }
        }

        if (!more) break;
        __syncthreads();
    }

    // epilogue
#pragma unroll
    for (int mt = 0; mt < 2; mt++) {
#pragma unroll
        for (int nt = 0; nt < 4; nt++) {
            int row0 = bm + wm + mt * 16 + fr;
            int col0 = bn + wn + nt * 8 + (fc << 1);
#pragma unroll
            for (int h = 0; h < 2; h++) {
                int row = row0 + h * 8;
                float2 v;
                v.x = acc[mt][nt][2 * h + 0];
                v.y = acc[mt][nt][2 * h + 1];
                if (EPI == 1) {
                    float2 bv = *reinterpret_cast<const float2*>(bias + col0);
                    v.x += bv.x; v.y += bv.y;
                } else if (EPI == 2) {
                    const int2 e = *reinterpret_cast<const int2*>(
                        rel + (size_t)z * sR + (size_t)row * ldC + col0);
                    v.x = (e.x == 0) ? -1e10f : v.x * 0.0625f;
                    v.y = (e.y == 0) ? -1e10f : v.y * 0.0625f;
                }
                *reinterpret_cast<float2*>(C + (size_t)row * ldC + col0) = v;
            }
        }
    }
}

// ============================================================================
// Row softmax in place over rows of length N_ (2048). One block per row.
// ============================================================================
__global__ void __launch_bounds__(256) softmax_rows(float* __restrict__ S)
{
    __shared__ float red[8];
    float4* row = reinterpret_cast<float4*>(S + (size_t)blockIdx.x * N_);
    const int t = threadIdx.x;
    float4 v0 = row[t];
    float4 v1 = row[t + 256];

    float m = fmaxf(fmaxf(fmaxf(v0.x, v0.y), fmaxf(v0.z, v0.w)),
                    fmaxf(fmaxf(v1.x, v1.y), fmaxf(v1.z, v1.w)));
    m = warp_max(m);
    if ((t & 31) == 0) red[t >> 5] = m;
    __syncthreads();
    m = red[0];
#pragma unroll
    for (int i = 1; i < 8; i++) m = fmaxf(m, red[i]);
    __syncthreads();

    v0.x = expf(v0.x - m); v0.y = expf(v0.y - m);
    v0.z = expf(v0.z - m); v0.w = expf(v0.w - m);
    v1.x = expf(v1.x - m); v1.y = expf(v1.y - m);
    v1.z = expf(v1.z - m); v1.w = expf(v1.w - m);

    float s = warp_sum(v0.x + v0.y + v0.z + v0.w + v1.x + v1.y + v1.z + v1.w);
    if ((t & 31) == 0) red[t >> 5] = s;
    __syncthreads();
    s = red[0];
#pragma unroll
    for (int i = 1; i < 8; i++) s += red[i];
    const float inv = 1.0f / s;

    v0.x *= inv; v0.y *= inv; v0.z *= inv; v0.w *= inv;
    v1.x *= inv; v1.y *= inv; v1.z *= inv; v1.w *= inv;
    row[t] = v0;
    row[t + 256] = v1;
}

// ============================================================================
// out = LayerNorm(x + c2) * gamma + beta, rows of E_ (512). One block per row.
// ============================================================================
__global__ void __launch_bounds__(128) resid_ln(
    const float* __restrict__ x, const float* __restrict__ c2,
    const float* __restrict__ gam, const float* __restrict__ bet,
    float* __restrict__ out)
{
    __shared__ float red[4];
    const size_t base = (size_t)blockIdx.x * E_;
    const int t = threadIdx.x;
    float4 xv = *reinterpret_cast<const float4*>(x + base + (t << 2));
    float4 cv = *reinterpret_cast<const float4*>(c2 + base + (t << 2));
    float v0 = xv.x + cv.x, v1 = xv.y + cv.y, v2 = xv.z + cv.z, v3 = xv.w + cv.w;

    float s = warp_sum(v0 + v1 + v2 + v3);
    if ((t & 31) == 0) red[t >> 5] = s;
    __syncthreads();
    const float mean = (red[0] + red[1] + red[2] + red[3]) * (1.0f / E_);
    __syncthreads();

    float d0 = v0 - mean, d1 = v1 - mean, d2 = v2 - mean, d3 = v3 - mean;
    float ss = warp_sum(d0 * d0 + d1 * d1 + d2 * d2 + d3 * d3);
    if ((t & 31) == 0) red[t >> 5] = ss;
    __syncthreads();
    const float var = (red[0] + red[1] + red[2] + red[3]) * (1.0f / E_);
    const float r = rsqrtf(var + kLnEps);

    float4 gv = *reinterpret_cast<const float4*>(gam + (t << 2));
    float4 bv = *reinterpret_cast<const float4*>(bet + (t << 2));
    float4 o;
    o.x = d0 * r * gv.x + bv.x;
    o.y = d1 * r * gv.y + bv.y;
    o.z = d2 * r * gv.z + bv.z;
    o.w = d3 * r * gv.w + bv.w;
    *reinterpret_cast<float4*>(out + base + (t << 2)) = o;
}

// ============================================================================
// Launch
// ============================================================================
extern "C" void kernel_launch(void* const* d_in, const int* in_sizes, int n_in,
                              void* d_out, int out_size)
{
    const float* node = (const float*)d_in[0];
    const int*   rel  = (const int*)d_in[1];
    const float* Wq   = (const float*)d_in[2];
    const float* bq   = (const float*)d_in[3];
    const float* Wk   = (const float*)d_in[4];
    const float* bk   = (const float*)d_in[5];
    const float* Wc   = (const float*)d_in[6];
    const float* lng  = (const float*)d_in[7];
    const float* lnb  = (const float*)d_in[8];
    float* out = (float*)d_out;

    float *qp, *kp, *sp, *ctxp, *c2p, *xp;
    cudaGetSymbolAddress((void**)&qp,   g_q);
    cudaGetSymbolAddress((void**)&kp,   g_k);
    cudaGetSymbolAddress((void**)&sp,   g_s);
    cudaGetSymbolAddress((void**)&ctxp, g_ctx);
    cudaGetSymbolAddress((void**)&c2p,  g_c2);
    cudaGetSymbolAddress((void**)&xp,   g_x);

    const int M = B_ * N_;
    const float* x_in = node;
    for (int l = 0; l < L_; l++) {
        float* x_out = (l == L_ - 1) ? out : xp;

        // q = x Wq^T + bq ; k = x Wk^T + bk   (NT, bias)
        mma_gemm<true, 1><<<dim3(F_ / 64, M / 128, 1), 256>>>(
            x_in, Wq + (size_t)l * F_ * E_, bq + l * F_, nullptr,
            qp, E_, E_, F_, 0, 0, 0, 0);
        mma_gemm<true, 1><<<dim3(F_ / 64, M / 128, 1), 256>>>(
            x_in, Wk + (size_t)l * F_ * E_, bk + l * F_, nullptr,
            kp, E_, E_, F_, 0, 0, 0, 0);

        // scores = q k^T / 16, masked   (NT per batch, mask epilogue)
        mma_gemm<true, 2><<<dim3(N_ / 64, N_ / 128, B_), 256>>>(
            qp, kp, nullptr, rel,
            sp, F_, F_, N_,
            (long)N_ * F_, (long)N_ * F_, (long)N_ * N_, (long)N_ * N_);

        // softmax over keys
        softmax_rows<<<M, 256>>>(sp);

        // ctx = P @ x   (NN per batch)
        mma_gemm<false, 0><<<dim3(E_ / 64, N_ / 128, B_), 256>>>(
            sp, x_in, nullptr, nullptr,
            ctxp, N_, E_, E_,
            (long)N_ * N_, (long)N_ * E_, (long)N_ * E_, 0);

        // c2 = ctx Wc^T   (NT)
        mma_gemm<true, 0><<<dim3(E_ / 64, M / 128, 1), 256>>>(
            ctxp, Wc + (size_t)l * E_ * E_, nullptr, nullptr,
            c2p, E_, E_, E_, 0, 0, 0, 0);

        // x = LN(x + c2)
        resid_ln<<<M, 128>>>(x_in, c2p, lng + l * E_, lnb + l * E_, x_out);

        x_in = x_out;
    }
}

// round 6
// speedup vs baseline: 2.0836x; 1.7765x over previous
#include <cuda_runtime.h>
#include <cuda_bf16.h>
#include <cstdint>
#include <math.h>

#define B_ 8
#define N_ 2048
#define E_ 512
#define F_ 256
#define L_ 2

#define ROWB 80                 // padded row stride in bytes (64 B data + 16 pad)
#define ARRB (128 * ROWB)       // one operand array per stage = 10240 B
#define STGB (4 * ARRB)         // stage: Ah, Al, Bh, Bl = 40960 B
#define GSM  (2 * STGB)         // double buffered = 81920 B

static __device__ __constant__ float kLnEps = 1e-5f;

// ---------------------------------------------------------------------------
// Scratch (__device__ globals; no allocations allowed)
// ---------------------------------------------------------------------------
__device__ float         g_s  [B_ * N_ * N_];          // fp32 scores
__device__ __nv_bfloat16 g_ph [B_ * N_ * N_];          // probs hi
__device__ __nv_bfloat16 g_pl [B_ * N_ * N_];          // probs lo
__device__ __nv_bfloat16 g_qh [B_ * N_ * F_], g_ql[B_ * N_ * F_];
__device__ __nv_bfloat16 g_kh [B_ * N_ * F_], g_kl[B_ * N_ * F_];
__device__ __nv_bfloat16 g_xsh[B_ * N_ * E_], g_xsl[B_ * N_ * E_];   // x split
__device__ __nv_bfloat16 g_xth[B_ * N_ * E_], g_xtl[B_ * N_ * E_];   // x^T split
__device__ __nv_bfloat16 g_ch [B_ * N_ * E_], g_cl [B_ * N_ * E_];   // ctx split
__device__ float         g_c2 [B_ * N_ * E_];
__device__ float         g_x  [B_ * N_ * E_];
__device__ __nv_bfloat16 g_wqh[L_ * F_ * E_], g_wql[L_ * F_ * E_];
__device__ __nv_bfloat16 g_wkh[L_ * F_ * E_], g_wkl[L_ * F_ * E_];
__device__ __nv_bfloat16 g_wch[L_ * E_ * E_], g_wcl[L_ * E_ * E_];

// ---------------------------------------------------------------------------
// PTX helpers
// ---------------------------------------------------------------------------
__device__ __forceinline__ uint32_t smem_u32(const void* p) {
    uint32_t a;
    asm("{ .reg .u64 t; cvta.to.shared.u64 t, %1; cvt.u32.u64 %0, t; }"
        : "=r"(a) : "l"(p));
    return a;
}
__device__ __forceinline__ void cp16(uint32_t sa, const void* ga) {
    asm volatile("cp.async.ca.shared.global [%0], [%1], 16;"
                 :: "r"(sa), "l"(ga));
}
__device__ __forceinline__ void cp_commit() {
    asm volatile("cp.async.commit_group;" ::: "memory");
}
template <int NV>
__device__ __forceinline__ void cp_wait() {
    asm volatile("cp.async.wait_group %0;" :: "n"(NV) : "memory");
}

#define LDSM4(r, a)                                                           \
    asm volatile("ldmatrix.sync.aligned.m8n8.x4.shared.b16 {%0,%1,%2,%3},[%4];" \
                 : "=r"((r)[0]), "=r"((r)[1]), "=r"((r)[2]), "=r"((r)[3])     \
                 : "r"(a))

#define MMA16(d, a, b0, b1)                                                   \
    asm volatile(                                                             \
        "mma.sync.aligned.m16n8k16.row.col.f32.bf16.bf16.f32 "                \
        "{%0,%1,%2,%3},{%4,%5,%6,%7},{%8,%9},{%0,%1,%2,%3};"                  \
        : "+f"((d)[0]), "+f"((d)[1]), "+f"((d)[2]), "+f"((d)[3])              \
        : "r"((a)[0]), "r"((a)[1]), "r"((a)[2]), "r"((a)[3]),                 \
          "r"(b0), "r"(b1))

__device__ __forceinline__ float warp_max(float v) {
#pragma unroll
    for (int o = 16; o > 0; o >>= 1) v = fmaxf(v, __shfl_xor_sync(0xffffffffu, v, o));
    return v;
}
__device__ __forceinline__ float warp_sum(float v) {
#pragma unroll
    for (int o = 16; o > 0; o >>= 1) v += __shfl_xor_sync(0xffffffffu, v, o);
    return v;
}

// ---------------------------------------------------------------------------
// bf16 split GEMM:  D[128x128] = (Ah+Al)[128,K] * ((Bh+Bl)[128,K])^T  (3-pass)
//   EPI: 0 = +bias, split-bf16 out   1 = mask+scale, fp32 out
//        2 = split-bf16 out          3 = fp32 out
// grid = (Ntile, Mtile, Z), 256 threads (8 warps, 4x2 of 32x64 warp tiles).
// ---------------------------------------------------------------------------
template <int EPI>
__global__ void __launch_bounds__(256) gemm_bf16(
    const __nv_bfloat16* __restrict__ Ah, const __nv_bfloat16* __restrict__ Al,
    int ldA, long sAz,
    const __nv_bfloat16* __restrict__ Bh, const __nv_bfloat16* __restrict__ Bl,
    int ldB, long sBz, int K,
    const float* __restrict__ bias, const int* __restrict__ rel, long sRz,
    float* __restrict__ outF, __nv_bfloat16* __restrict__ outH,
    __nv_bfloat16* __restrict__ outL, int ldC, long sCz)
{
    extern __shared__ char sm[];
    const uint32_t sbase = smem_u32(sm);
    const int tid = threadIdx.x, lane = tid & 31, wid = tid >> 5;
    const int z = blockIdx.z;
    const int bm = blockIdx.y * 128, bn = blockIdx.x * 128;
    Ah += (size_t)z * sAz;  Al += (size_t)z * sAz;
    Bh += (size_t)z * sBz;  Bl += (size_t)z * sBz;

    const int wm = (wid & 3) * 32, wn = (wid >> 2) * 64;

    // loader mapping: thread -> one array, 8 x 16B chunks (2 rows x 4 quarters)
    const int arr  = tid >> 6;           // 0:Ah 1:Al 2:Bh 3:Bl
    const int idx0 = (tid & 63) * 8;     // 64 threads x 8 chunks = 512 = 128 rows x 4
    const __nv_bfloat16* gsrc;
    int gld, growbase;
    if      (arr == 0) { gsrc = Ah; gld = ldA; growbase = bm; }
    else if (arr == 1) { gsrc = Al; gld = ldA; growbase = bm; }
    else if (arr == 2) { gsrc = Bh; gld = ldB; growbase = bn; }
    else               { gsrc = Bl; gld = ldB; growbase = bn; }

    float acc[2][8][4];
#pragma unroll
    for (int i = 0; i < 2; i++)
#pragma unroll
        for (int j = 0; j < 8; j++)
#pragma unroll
            for (int p = 0; p < 4; p++) acc[i][j][p] = 0.0f;

    const int nk = K / 32;

    // ---- prologue: stage 0
    {
        const uint32_t sdst = sbase + arr * ARRB;
#pragma unroll
        for (int j = 0; j < 8; j++) {
            const int idx = idx0 + j, row = idx >> 2, q = idx & 3;
            cp16(sdst + row * ROWB + q * 16,
                 gsrc + (size_t)(growbase + row) * gld + q * 8);
        }
        cp_commit();
    }

    int buf = 0;
    for (int kc = 0; kc < nk; kc++) {
        if (kc + 1 < nk) {
            const int k0 = (kc + 1) * 32;
            const uint32_t sdst = sbase + (buf ^ 1) * STGB + arr * ARRB;
#pragma unroll
            for (int j = 0; j < 8; j++) {
                const int idx = idx0 + j, row = idx >> 2, q = idx & 3;
                cp16(sdst + row * ROWB + q * 16,
                     gsrc + (size_t)(growbase + row) * gld + k0 + q * 8);
            }
            cp_commit();
            cp_wait<1>();
        } else {
            cp_wait<0>();
        }
        __syncthreads();

        const uint32_t st = sbase + buf * STGB;
#pragma unroll
        for (int ks = 0; ks < 2; ks++) {
            const int kb = ks * 32;     // 16 bf16 = 32 bytes per k16 step
            uint32_t ah[2][4], al[2][4], bh[4][4], bl[4][4];
#pragma unroll
            for (int mt = 0; mt < 2; mt++) {
                const uint32_t ra = st +
                    (uint32_t)(wm + mt * 16 + (lane & 15)) * ROWB +
                    kb + (lane >> 4) * 16;
                LDSM4(ah[mt], ra);
                LDSM4(al[mt], ra + ARRB);
            }
            const int g = lane >> 3;
#pragma unroll
            for (int ng = 0; ng < 4; ng++) {
                const uint32_t rb = st + 2 * ARRB +
                    (uint32_t)(wn + ng * 16 + ((g >> 1) << 3) + (lane & 7)) * ROWB +
                    kb + (g & 1) * 16;
                LDSM4(bh[ng], rb);
                LDSM4(bl[ng], rb + ARRB);
            }
#pragma unroll
            for (int mt = 0; mt < 2; mt++)
#pragma unroll
                for (int ng = 0; ng < 4; ng++) {
                    MMA16(acc[mt][2 * ng],     ah[mt], bh[ng][0], bh[ng][1]);
                    MMA16(acc[mt][2 * ng + 1], ah[mt], bh[ng][2], bh[ng][3]);
                    MMA16(acc[mt][2 * ng],     al[mt], bh[ng][0], bh[ng][1]);
                    MMA16(acc[mt][2 * ng + 1], al[mt], bh[ng][2], bh[ng][3]);
                    MMA16(acc[mt][2 * ng],     ah[mt], bl[ng][0], bl[ng][1]);
                    MMA16(acc[mt][2 * ng + 1], ah[mt], bl[ng][2], bl[ng][3]);
                }
        }
        __syncthreads();
        buf ^= 1;
    }

    // ---- epilogue
#pragma unroll
    for (int mt = 0; mt < 2; mt++)
#pragma unroll
        for (int nt = 0; nt < 8; nt++) {
            const int r0 = bm + wm + mt * 16 + (lane >> 2);
            const int c0 = bn + wn + nt * 8 + 2 * (lane & 3);
            float v0 = acc[mt][nt][0], v1 = acc[mt][nt][1];
            float v2 = acc[mt][nt][2], v3 = acc[mt][nt][3];
            if (EPI == 0) {
                const float b0 = bias[c0], b1 = bias[c0 + 1];
                v0 += b0; v1 += b1; v2 += b0; v3 += b1;
            }
#pragma unroll
            for (int h = 0; h < 2; h++) {
                const int row = r0 + h * 8;
                float x0 = h ? v2 : v0, x1 = h ? v3 : v1;
                const size_t base = (size_t)z * sCz + (size_t)row * ldC + c0;
                if (EPI == 1) {
                    const int2 e = *(const int2*)(rel + (size_t)z * sRz +
                                                  (size_t)row * ldC + c0);
                    float2 o;
                    o.x = (e.x == 0) ? -1e10f : x0 * 0.0625f;
                    o.y = (e.y == 0) ? -1e10f : x1 * 0.0625f;
                    *(float2*)(outF + base) = o;
                } else if (EPI == 3) {
                    float2 o; o.x = x0; o.y = x1;
                    *(float2*)(outF + base) = o;
                } else {
                    __nv_bfloat162 hv, lv;
                    hv.x = __float2bfloat16(x0);
                    hv.y = __float2bfloat16(x1);
                    lv.x = __float2bfloat16(x0 - __bfloat162float(hv.x));
                    lv.y = __float2bfloat16(x1 - __bfloat162float(hv.y));
                    *(__nv_bfloat162*)(outH + base) = hv;
                    *(__nv_bfloat162*)(outL + base) = lv;
                }
            }
        }
}

// ---------------------------------------------------------------------------
// Elementwise split: fp32 -> bf16 hi/lo (vectorized by 4)
// ---------------------------------------------------------------------------
__global__ void __launch_bounds__(256) split4(
    const float* __restrict__ s, __nv_bfloat16* __restrict__ h,
    __nv_bfloat16* __restrict__ l, int n4)
{
    int i = blockIdx.x * 256 + threadIdx.x;
    if (i >= n4) return;
    float4 v = ((const float4*)s)[i];
    __nv_bfloat162 h0, h1, l0, l1;
    h0.x = __float2bfloat16(v.x); h0.y = __float2bfloat16(v.y);
    h1.x = __float2bfloat16(v.z); h1.y = __float2bfloat16(v.w);
    l0.x = __float2bfloat16(v.x - __bfloat162float(h0.x));
    l0.y = __float2bfloat16(v.y - __bfloat162float(h0.y));
    l1.x = __float2bfloat16(v.z - __bfloat162float(h1.x));
    l1.y = __float2bfloat16(v.w - __bfloat162float(h1.y));
    ((__nv_bfloat162*)h)[2 * i]     = h0;
    ((__nv_bfloat162*)h)[2 * i + 1] = h1;
    ((__nv_bfloat162*)l)[2 * i]     = l0;
    ((__nv_bfloat162*)l)[2 * i + 1] = l1;
}

// ---------------------------------------------------------------------------
// Transpose + split: x[z][n][d] fp32 -> xT hi/lo [z][d][n] bf16
// block (32,8), grid (E/32, N/32, B)
// ---------------------------------------------------------------------------
__global__ void __launch_bounds__(256) transpose_split(
    const float* __restrict__ x, __nv_bfloat16* __restrict__ th,
    __nv_bfloat16* __restrict__ tl)
{
    __shared__ float tile[32][33];
    const int z = blockIdx.z;
    const int d0 = blockIdx.x * 32, n0 = blockIdx.y * 32;
    const int tx = threadIdx.x, ty = threadIdx.y;
    const float* xb = x + (size_t)z * N_ * E_;
#pragma unroll
    for (int i = 0; i < 32; i += 8)
        tile[ty + i][tx] = xb[(size_t)(n0 + ty + i) * E_ + d0 + tx];
    __syncthreads();
    __nv_bfloat16* thb = th + (size_t)z * E_ * N_;
    __nv_bfloat16* tlb = tl + (size_t)z * E_ * N_;
#pragma unroll
    for (int i = 0; i < 32; i += 8) {
        const float v = tile[tx][ty + i];
        const __nv_bfloat16 hb = __float2bfloat16(v);
        const size_t o = (size_t)(d0 + ty + i) * N_ + n0 + tx;
        thb[o] = hb;
        tlb[o] = __float2bfloat16(v - __bfloat162float(hb));
    }
}

// ---------------------------------------------------------------------------
// Row softmax over N_ (2048) + split-bf16 output. One block per row.
// ---------------------------------------------------------------------------
__global__ void __launch_bounds__(256) softmax_split(
    const float* __restrict__ S, __nv_bfloat16* __restrict__ Ph,
    __nv_bfloat16* __restrict__ Pl)
{
    __shared__ float red[8];
    const float4* row = reinterpret_cast<const float4*>(S + (size_t)blockIdx.x * N_);
    const int t = threadIdx.x;
    float4 v0 = row[t];
    float4 v1 = row[t + 256];

    float m = fmaxf(fmaxf(fmaxf(v0.x, v0.y), fmaxf(v0.z, v0.w)),
                    fmaxf(fmaxf(v1.x, v1.y), fmaxf(v1.z, v1.w)));
    m = warp_max(m);
    if ((t & 31) == 0) red[t >> 5] = m;
    __syncthreads();
    m = red[0];
#pragma unroll
    for (int i = 1; i < 8; i++) m = fmaxf(m, red[i]);
    __syncthreads();

    v0.x = expf(v0.x - m); v0.y = expf(v0.y - m);
    v0.z = expf(v0.z - m); v0.w = expf(v0.w - m);
    v1.x = expf(v1.x - m); v1.y = expf(v1.y - m);
    v1.z = expf(v1.z - m); v1.w = expf(v1.w - m);

    float s = warp_sum(v0.x + v0.y + v0.z + v0.w + v1.x + v1.y + v1.z + v1.w);
    if ((t & 31) == 0) red[t >> 5] = s;
    __syncthreads();
    s = red[0];
#pragma unroll
    for (int i = 1; i < 8; i++) s += red[i];
    const float inv = 1.0f / s;

    __nv_bfloat162* ph2 = (__nv_bfloat162*)(Ph + (size_t)blockIdx.x * N_);
    __nv_bfloat162* pl2 = (__nv_bfloat162*)(Pl + (size_t)blockIdx.x * N_);
    float e[8] = {v0.x * inv, v0.y * inv, v0.z * inv, v0.w * inv,
                  v1.x * inv, v1.y * inv, v1.z * inv, v1.w * inv};
#pragma unroll
    for (int g = 0; g < 2; g++) {
#pragma unroll
        for (int p = 0; p < 2; p++) {
            __nv_bfloat162 hv, lv;
            const float a = e[g * 4 + p * 2], b = e[g * 4 + p * 2 + 1];
            hv.x = __float2bfloat16(a); hv.y = __float2bfloat16(b);
            lv.x = __float2bfloat16(a - __bfloat162float(hv.x));
            lv.y = __float2bfloat16(b - __bfloat162float(hv.y));
            const int idx = g * 512 + 2 * t + p;
            ph2[idx] = hv;
            pl2[idx] = lv;
        }
    }
}

// ---------------------------------------------------------------------------
// out = LayerNorm(x + c2) * gamma + beta, rows of E_ (512). One block per row.
// ---------------------------------------------------------------------------
__global__ void __launch_bounds__(128) resid_ln(
    const float* __restrict__ x, const float* __restrict__ c2,
    const float* __restrict__ gam, const float* __restrict__ bet,
    float* __restrict__ out)
{
    __shared__ float red[4];
    const size_t base = (size_t)blockIdx.x * E_;
    const int t = threadIdx.x;
    float4 xv = *reinterpret_cast<const float4*>(x + base + (t << 2));
    float4 cv = *reinterpret_cast<const float4*>(c2 + base + (t << 2));
    float v0 = xv.x + cv.x, v1 = xv.y + cv.y, v2 = xv.z + cv.z, v3 = xv.w + cv.w;

    float s = warp_sum(v0 + v1 + v2 + v3);
    if ((t & 31) == 0) red[t >> 5] = s;
    __syncthreads();
    const float mean = (red[0] + red[1] + red[2] + red[3]) * (1.0f / E_);
    __syncthreads();

    float d0 = v0 - mean, d1 = v1 - mean, d2 = v2 - mean, d3 = v3 - mean;
    float ss = warp_sum(d0 * d0 + d1 * d1 + d2 * d2 + d3 * d3);
    if ((t & 31) == 0) red[t >> 5] = ss;
    __syncthreads();
    const float var = (red[0] + red[1] + red[2] + red[3]) * (1.0f / E_);
    const float r = rsqrtf(var + kLnEps);

    float4 gv = *reinterpret_cast<const float4*>(gam + (t << 2));
    float4 bv = *reinterpret_cast<const float4*>(bet + (t << 2));
    float4 o;
    o.x = d0 * r * gv.x + bv.x;
    o.y = d1 * r * gv.y + bv.y;
    o.z = d2 * r * gv.z + bv.z;
    o.w = d3 * r * gv.w + bv.w;
    *reinterpret_cast<float4*>(out + base + (t << 2)) = o;
}

// ---------------------------------------------------------------------------
// Launch
// ---------------------------------------------------------------------------
extern "C" void kernel_launch(void* const* d_in, const int* in_sizes, int n_in,
                              void* d_out, int out_size)
{
    const float* node = (const float*)d_in[0];
    const int*   rel  = (const int*)d_in[1];
    const float* Wq   = (const float*)d_in[2];
    const float* bq   = (const float*)d_in[3];
    const float* Wk   = (const float*)d_in[4];
    const float* bk   = (const float*)d_in[5];
    const float* Wc   = (const float*)d_in[6];
    const float* lng  = (const float*)d_in[7];
    const float* lnb  = (const float*)d_in[8];
    float* out = (float*)d_out;

    cudaFuncSetAttribute(gemm_bf16<0>, cudaFuncAttributeMaxDynamicSharedMemorySize, GSM);
    cudaFuncSetAttribute(gemm_bf16<1>, cudaFuncAttributeMaxDynamicSharedMemorySize, GSM);
    cudaFuncSetAttribute(gemm_bf16<2>, cudaFuncAttributeMaxDynamicSharedMemorySize, GSM);
    cudaFuncSetAttribute(gemm_bf16<3>, cudaFuncAttributeMaxDynamicSharedMemorySize, GSM);

    float *sp, *c2p, *xp;
    __nv_bfloat16 *php, *plp, *qhp, *qlp, *khp, *klp;
    __nv_bfloat16 *xshp, *xslp, *xthp, *xtlp, *chp, *clp;
    __nv_bfloat16 *wqh, *wql, *wkh, *wkl, *wch, *wcl;
    cudaGetSymbolAddress((void**)&sp,   g_s);
    cudaGetSymbolAddress((void**)&c2p,  g_c2);
    cudaGetSymbolAddress((void**)&xp,   g_x);
    cudaGetSymbolAddress((void**)&php,  g_ph);
    cudaGetSymbolAddress((void**)&plp,  g_pl);
    cudaGetSymbolAddress((void**)&qhp,  g_qh);
    cudaGetSymbolAddress((void**)&qlp,  g_ql);
    cudaGetSymbolAddress((void**)&khp,  g_kh);
    cudaGetSymbolAddress((void**)&klp,  g_kl);
    cudaGetSymbolAddress((void**)&xshp, g_xsh);
    cudaGetSymbolAddress((void**)&xslp, g_xsl);
    cudaGetSymbolAddress((void**)&xthp, g_xth);
    cudaGetSymbolAddress((void**)&xtlp, g_xtl);
    cudaGetSymbolAddress((void**)&chp,  g_ch);
    cudaGetSymbolAddress((void**)&clp,  g_cl);
    cudaGetSymbolAddress((void**)&wqh,  g_wqh);
    cudaGetSymbolAddress((void**)&wql,  g_wql);
    cudaGetSymbolAddress((void**)&wkh,  g_wkh);
    cudaGetSymbolAddress((void**)&wkl,  g_wkl);
    cudaGetSymbolAddress((void**)&wch,  g_wch);
    cudaGetSymbolAddress((void**)&wcl,  g_wcl);

    // split weights (all layers)
    split4<<<(L_ * F_ * E_ / 4 + 255) / 256, 256>>>(Wq, wqh, wql, L_ * F_ * E_ / 4);
    split4<<<(L_ * F_ * E_ / 4 + 255) / 256, 256>>>(Wk, wkh, wkl, L_ * F_ * E_ / 4);
    split4<<<(L_ * E_ * E_ / 4 + 255) / 256, 256>>>(Wc, wch, wcl, L_ * E_ * E_ / 4);

    const int M = B_ * N_;
    const float* x_in = node;
    for (int l = 0; l < L_; l++) {
        float* x_out = (l == L_ - 1) ? out : xp;

        // x splits (row-major + transposed)
        split4<<<(M * E_ / 4 + 255) / 256, 256>>>(x_in, xshp, xslp, M * E_ / 4);
        transpose_split<<<dim3(E_ / 32, N_ / 32, B_), dim3(32, 8)>>>(x_in, xthp, xtlp);

        // q = x Wq^T + bq ; k = x Wk^T + bk
        gemm_bf16<0><<<dim3(F_ / 128, M / 128, 1), 256, GSM>>>(
            xshp, xslp, E_, 0,
            wqh + (size_t)l * F_ * E_, wql + (size_t)l * F_ * E_, E_, 0,
            E_, bq + l * F_, nullptr, 0, nullptr, qhp, qlp, F_, 0);
        gemm_bf16<0><<<dim3(F_ / 128, M / 128, 1), 256, GSM>>>(
            xshp, xslp, E_, 0,
            wkh + (size_t)l * F_ * E_, wkl + (size_t)l * F_ * E_, E_, 0,
            E_, bk + l * F_, nullptr, 0, nullptr, khp, klp, F_, 0);

        // scores = q k^T / 16, masked
        gemm_bf16<1><<<dim3(N_ / 128, N_ / 128, B_), 256, GSM>>>(
            qhp, qlp, F_, (long)N_ * F_, khp, klp, F_, (long)N_ * F_,
            F_, nullptr, rel, (long)N_ * N_, sp, nullptr, nullptr, N_,
            (long)N_ * N_);

        // softmax + split
        softmax_split<<<M, 256>>>(sp, php, plp);

        // ctx = P @ x  (B operand = x^T hi/lo, K-major over n)
        gemm_bf16<2><<<dim3(E_ / 128, N_ / 128, B_), 256, GSM>>>(
            php, plp, N_, (long)N_ * N_, xthp, xtlp, N_, (long)E_ * N_,
            N_, nullptr, nullptr, 0, nullptr, chp, clp, E_, (long)N_ * E_);

        // c2 = ctx Wc^T
        gemm_bf16<3><<<dim3(E_ / 128, M / 128, 1), 256, GSM>>>(
            chp, clp, E_, 0,
            wch + (size_t)l * E_ * E_, wcl + (size_t)l * E_ * E_, E_, 0,
            E_, nullptr, nullptr, 0, c2p, nullptr, nullptr, E_, 0);

        // x = LN(x + c2)
        resid_ln<<<M, 128>>>(x_in, c2p, lng + l * E_, lnb + l * E_, x_out);

        x_in = x_out;
    }
}